// round 1
// baseline (speedup 1.0000x reference)
#include <cuda_runtime.h>
#include <cstdint>

// Problem constants
static constexpr int Lc  = 2048;
static constexpr int Bc  = 8;
static constexpr int Dc  = 1024;
static constexpr int Hc  = 16;
static constexpr int dhc = 64;          // Dc / Hc
static constexpr int Nmix = Bc * dhc;   // 512

// Scratch (device globals; allocation-free per harness rules)
__device__ float g_nw[(size_t)Hc * Lc * Lc];     // 256 MiB normalized weights (tf32-rounded)
__device__ float g_xr[(size_t)Bc * Lc * Dc];     // 64 MiB  x rounded to tf32
__device__ float g_wpr[(size_t)Dc * Dc];         // 4 MiB   W_proj rounded to tf32
__device__ float g_mixed[(size_t)Bc * Lc * Dc];  // 64 MiB  mixing output (tf32-rounded)

__device__ __forceinline__ float tf32r(float x) {
    uint32_t u;
    asm("cvt.rna.tf32.f32 %0, %1;" : "=r"(u) : "f"(x));
    return __uint_as_float(u);
}

__device__ __forceinline__ void cpa16(void* smem, const void* g) {
    uint32_t s = (uint32_t)__cvta_generic_to_shared(smem);
    asm volatile("cp.async.cg.shared.global [%0], [%1], 16;\n" :: "r"(s), "l"(g) : "memory");
}
__device__ __forceinline__ void cp_commit() {
    asm volatile("cp.async.commit_group;\n" ::: "memory");
}

#define MMA_TF32(d, a, b) \
    asm volatile("mma.sync.aligned.m16n8k8.row.col.f32.tf32.tf32.f32 " \
        "{%0,%1,%2,%3}, {%4,%5,%6,%7}, {%8,%9}, {%0,%1,%2,%3};" \
        : "+f"((d)[0]), "+f"((d)[1]), "+f"((d)[2]), "+f"((d)[3]) \
        : "r"((a)[0]), "r"((a)[1]), "r"((a)[2]), "r"((a)[3]), \
          "r"((b)[0]), "r"((b)[1]))

// ---------------------------------------------------------------------------
// Round fp32 -> tf32 (rna) elementwise, vectorized
// ---------------------------------------------------------------------------
__global__ void round_tf32_kernel(const float* __restrict__ src,
                                  float* __restrict__ dst, int n4) {
    int i = blockIdx.x * blockDim.x + threadIdx.x;
    if (i < n4) {
        float4 v = reinterpret_cast<const float4*>(src)[i];
        v.x = tf32r(v.x); v.y = tf32r(v.y); v.z = tf32r(v.z); v.w = tf32r(v.w);
        reinterpret_cast<float4*>(dst)[i] = v;
    }
}

// ---------------------------------------------------------------------------
// Fused masked-softmax row kernel. One block per (h, i) row.
//   Z = (L-1-i) + sum_{l<=i} exp(W[h,i,l])
//   nw[l] = (l<=i ? exp(W[h,i,l]) : 1) / Z,  stored tf32-rounded
// ---------------------------------------------------------------------------
__global__ void softmax_rows_kernel(const float* __restrict__ W) {
    const int row = blockIdx.x;                 // h*L + i
    const int i = row & (Lc - 1);
    const float* wr = W + (size_t)row * Lc;
    float* outp = g_nw + (size_t)row * Lc;

    float s = 0.f;
    for (int l = threadIdx.x; l <= i; l += blockDim.x) s += __expf(wr[l]);

    __shared__ float red[9];
    #pragma unroll
    for (int o = 16; o; o >>= 1) s += __shfl_xor_sync(0xffffffffu, s, o);
    if ((threadIdx.x & 31) == 0) red[threadIdx.x >> 5] = s;
    __syncthreads();
    if (threadIdx.x < 32) {
        float v = (threadIdx.x < 8) ? red[threadIdx.x] : 0.f;
        #pragma unroll
        for (int o = 4; o; o >>= 1) v += __shfl_xor_sync(0xffffffffu, v, o);
        if (threadIdx.x == 0) red[8] = 1.f / (v + (float)(Lc - 1 - i));
    }
    __syncthreads();
    const float invZ = red[8];
    for (int l = threadIdx.x; l < Lc; l += blockDim.x) {
        float val = (l <= i) ? __expf(wr[l]) * invZ : invZ;
        outp[l] = tf32r(val);
    }
}

// ---------------------------------------------------------------------------
// GEMM 1: per-head mixing.  C[i, n] = sum_l NW_h[i, l] * X[b, l, h*64+dd],
// n = b*64+dd.  M=2048, N=512, K=2048, tf32 mma, 128x128x32 tiles.
// ---------------------------------------------------------------------------
__global__ void __launch_bounds__(256, 2) gemm_mix_kernel() {
    constexpr int BM = 128, BN = 128, BK = 32;
    constexpr int AP = BK + 4;   // As pitch (floats)
    constexpr int BP = BN + 8;   // Bs pitch (floats)
    extern __shared__ float sm[];
    float (*As)[BM][AP] = reinterpret_cast<float (*)[BM][AP]>(sm);
    float (*Bs)[BK][BP] = reinterpret_cast<float (*)[BK][BP]>(sm + 2 * BM * AP);

    const int h  = blockIdx.z;
    const int m0 = blockIdx.y * BM;
    const int n0 = blockIdx.x * BN;
    const int tid = threadIdx.x;
    const int lane = tid & 31, warp = tid >> 5;
    const int wm = warp & 3, wn = warp >> 2;

    const float* Ag = g_nw + (size_t)h * Lc * Lc;
    const int ar = tid >> 3;            // A: 0..31 row-in-pass
    const int ac = (tid & 7) * 4;       // A: col
    const int br = tid >> 5;            // B: 0..7 k-row-in-pass
    const int bc = (tid & 31) * 4;      // B: n col
    const int nb = (n0 + bc) >> 6;      // batch
    const int dd = (n0 + bc) & 63;
    const float* Bg = g_xr + (size_t)nb * Lc * Dc + (size_t)h * dhc + dd;

    float acc[2][8][4];
    #pragma unroll
    for (int a = 0; a < 2; a++)
        #pragma unroll
        for (int b = 0; b < 8; b++)
            #pragma unroll
            for (int c = 0; c < 4; c++) acc[a][b][c] = 0.f;

    const int nkt = Lc / BK;            // 64

    auto load_tiles = [&](int buf, int kt) {
        #pragma unroll
        for (int p = 0; p < 4; p++) {
            int row = p * 32 + ar;
            cpa16(&As[buf][row][ac], Ag + (size_t)(m0 + row) * Lc + kt * BK + ac);
        }
        #pragma unroll
        for (int p = 0; p < 4; p++) {
            int krow = p * 8 + br;
            cpa16(&Bs[buf][krow][bc], Bg + (size_t)(kt * BK + krow) * Dc);
        }
        cp_commit();
    };

    load_tiles(0, 0);
    for (int kt = 0; kt < nkt; kt++) {
        const int buf = kt & 1;
        if (kt + 1 < nkt) {
            load_tiles(buf ^ 1, kt + 1);
            asm volatile("cp.async.wait_group 1;\n" ::: "memory");
        } else {
            asm volatile("cp.async.wait_group 0;\n" ::: "memory");
        }
        __syncthreads();

        const int r = lane >> 2, c = lane & 3;
        #pragma unroll
        for (int ks = 0; ks < 4; ks++) {
            const int kc = ks * 8;
            uint32_t afr[2][4], bfr[8][2];
            #pragma unroll
            for (int mt = 0; mt < 2; mt++) {
                const int rb = wm * 32 + mt * 16;
                afr[mt][0] = __float_as_uint(As[buf][rb + r][kc + c]);
                afr[mt][1] = __float_as_uint(As[buf][rb + r + 8][kc + c]);
                afr[mt][2] = __float_as_uint(As[buf][rb + r][kc + c + 4]);
                afr[mt][3] = __float_as_uint(As[buf][rb + r + 8][kc + c + 4]);
            }
            #pragma unroll
            for (int nt = 0; nt < 8; nt++) {
                const int cb = wn * 64 + nt * 8;
                bfr[nt][0] = __float_as_uint(Bs[buf][kc + c][cb + r]);
                bfr[nt][1] = __float_as_uint(Bs[buf][kc + c + 4][cb + r]);
            }
            #pragma unroll
            for (int mt = 0; mt < 2; mt++)
                #pragma unroll
                for (int nt = 0; nt < 8; nt++)
                    MMA_TF32(acc[mt][nt], afr[mt], bfr[nt]);
        }
        __syncthreads();
    }

    // epilogue: write mixed[b, i, h*64+dd], tf32-rounded for GEMM2
    const int r = lane >> 2, c2 = (lane & 3) * 2;
    #pragma unroll
    for (int mt = 0; mt < 2; mt++) {
        #pragma unroll
        for (int nt = 0; nt < 8; nt++) {
            const int row = m0 + wm * 32 + mt * 16 + r;
            const int col = n0 + wn * 64 + nt * 8 + c2;
            const int b = col >> 6, d0 = col & 63;
            float* o0 = g_mixed + ((size_t)b * Lc + row) * Dc + h * dhc + d0;
            o0[0] = tf32r(acc[mt][nt][0]);
            o0[1] = tf32r(acc[mt][nt][1]);
            float* o1 = o0 + 8 * Dc;
            o1[0] = tf32r(acc[mt][nt][2]);
            o1[1] = tf32r(acc[mt][nt][3]);
        }
    }
}

// ---------------------------------------------------------------------------
// GEMM 2: projection.  out[m, j] = sum_k mixed[m, k] * W_proj[j, k] + b[j]
// M=16384, N=1024, K=1024.
// ---------------------------------------------------------------------------
__global__ void __launch_bounds__(256, 2) gemm_proj_kernel(
    const float* __restrict__ bias, float* __restrict__ out) {
    constexpr int BM = 128, BN = 128, BK = 32;
    constexpr int AP = BK + 4;
    extern __shared__ float sm[];
    float (*As)[BM][AP] = reinterpret_cast<float (*)[BM][AP]>(sm);
    float (*Bs)[BN][AP] = reinterpret_cast<float (*)[BN][AP]>(sm + 2 * BM * AP);

    const int m0 = blockIdx.y * BM;
    const int n0 = blockIdx.x * BN;
    const int tid = threadIdx.x;
    const int lane = tid & 31, warp = tid >> 5;
    const int wm = warp & 3, wn = warp >> 2;

    const int ar = tid >> 3;
    const int ac = (tid & 7) * 4;

    float acc[2][8][4];
    #pragma unroll
    for (int a = 0; a < 2; a++)
        #pragma unroll
        for (int b = 0; b < 8; b++)
            #pragma unroll
            for (int c = 0; c < 4; c++) acc[a][b][c] = 0.f;

    const int nkt = Dc / BK;            // 32

    auto load_tiles = [&](int buf, int kt) {
        #pragma unroll
        for (int p = 0; p < 4; p++) {
            int row = p * 32 + ar;
            cpa16(&As[buf][row][ac], g_mixed + (size_t)(m0 + row) * Dc + kt * BK + ac);
            cpa16(&Bs[buf][row][ac], g_wpr   + (size_t)(n0 + row) * Dc + kt * BK + ac);
        }
        cp_commit();
    };

    load_tiles(0, 0);
    for (int kt = 0; kt < nkt; kt++) {
        const int buf = kt & 1;
        if (kt + 1 < nkt) {
            load_tiles(buf ^ 1, kt + 1);
            asm volatile("cp.async.wait_group 1;\n" ::: "memory");
        } else {
            asm volatile("cp.async.wait_group 0;\n" ::: "memory");
        }
        __syncthreads();

        const int r = lane >> 2, c = lane & 3;
        #pragma unroll
        for (int ks = 0; ks < 4; ks++) {
            const int kc = ks * 8;
            uint32_t afr[2][4], bfr[8][2];
            #pragma unroll
            for (int mt = 0; mt < 2; mt++) {
                const int rb = wm * 32 + mt * 16;
                afr[mt][0] = __float_as_uint(As[buf][rb + r][kc + c]);
                afr[mt][1] = __float_as_uint(As[buf][rb + r + 8][kc + c]);
                afr[mt][2] = __float_as_uint(As[buf][rb + r][kc + c + 4]);
                afr[mt][3] = __float_as_uint(As[buf][rb + r + 8][kc + c + 4]);
            }
            #pragma unroll
            for (int nt = 0; nt < 8; nt++) {
                const int cb = wn * 64 + nt * 8;
                bfr[nt][0] = __float_as_uint(Bs[buf][cb + r][kc + c]);
                bfr[nt][1] = __float_as_uint(Bs[buf][cb + r][kc + c + 4]);
            }
            #pragma unroll
            for (int mt = 0; mt < 2; mt++)
                #pragma unroll
                for (int nt = 0; nt < 8; nt++)
                    MMA_TF32(acc[mt][nt], afr[mt], bfr[nt]);
        }
        __syncthreads();
    }

    const int r = lane >> 2, c2 = (lane & 3) * 2;
    #pragma unroll
    for (int mt = 0; mt < 2; mt++) {
        #pragma unroll
        for (int nt = 0; nt < 8; nt++) {
            const int row = m0 + wm * 32 + mt * 16 + r;
            const int col = n0 + wn * 64 + nt * 8 + c2;
            const float bz0 = bias[col], bz1 = bias[col + 1];
            float* o0 = out + (size_t)row * Dc + col;
            o0[0] = acc[mt][nt][0] + bz0;
            o0[1] = acc[mt][nt][1] + bz1;
            float* o1 = o0 + 8 * Dc;
            o1[0] = acc[mt][nt][2] + bz0;
            o1[1] = acc[mt][nt][3] + bz1;
        }
    }
}

// ---------------------------------------------------------------------------
extern "C" void kernel_launch(void* const* d_in, const int* in_sizes, int n_in,
                              void* d_out, int out_size) {
    const float* x  = (const float*)d_in[0];
    const float* W  = (const float*)d_in[1];
    const float* Wp = (const float*)d_in[2];
    const float* bp = (const float*)d_in[3];
    float* out = (float*)d_out;

    float *xr_p = nullptr, *wpr_p = nullptr;
    cudaGetSymbolAddress((void**)&xr_p, g_xr);
    cudaGetSymbolAddress((void**)&wpr_p, g_wpr);

    constexpr int SMEM_MIX  = 2 * 128 * 36 * 4 + 2 * 32 * 136 * 4;   // 71680
    constexpr int SMEM_PROJ = 2 * 128 * 36 * 4 + 2 * 128 * 36 * 4;   // 73728
    cudaFuncSetAttribute(gemm_mix_kernel,
                         cudaFuncAttributeMaxDynamicSharedMemorySize, SMEM_MIX);
    cudaFuncSetAttribute(gemm_proj_kernel,
                         cudaFuncAttributeMaxDynamicSharedMemorySize, SMEM_PROJ);

    // 1) round x, W_proj to tf32
    {
        int n4 = Bc * Lc * Dc / 4;
        round_tf32_kernel<<<(n4 + 255) / 256, 256>>>(x, xr_p, n4);
    }
    {
        int n4 = Dc * Dc / 4;
        round_tf32_kernel<<<(n4 + 255) / 256, 256>>>(Wp, wpr_p, n4);
    }
    // 2) masked softmax -> g_nw
    softmax_rows_kernel<<<Hc * Lc, 256>>>(W);
    // 3) per-head mixing GEMM -> g_mixed
    gemm_mix_kernel<<<dim3(Nmix / 128, Lc / 128, Hc), 256, SMEM_MIX>>>();
    // 4) projection GEMM + bias -> out
    gemm_proj_kernel<<<dim3(Dc / 128, (Bc * Lc) / 128), 256, SMEM_PROJ>>>(bp, out);
}

// round 2
// speedup vs baseline: 1.0959x; 1.0959x over previous
#include <cuda_runtime.h>
#include <cstdint>

// Problem constants
static constexpr int Lc  = 2048;
static constexpr int Bc  = 8;
static constexpr int Dc  = 1024;
static constexpr int Hc  = 16;
static constexpr int dhc = 64;          // Dc / Hc
static constexpr int Nmix = Bc * dhc;   // 512
static constexpr int SEGS = 16;         // L segments for suffix scan
static constexpr int SEGL = Lc / SEGS;  // 128

// Scratch (device globals; allocation-free per harness rules)
__device__ float g_nw[(size_t)Hc * Lc * Lc];     // exp(W), lower-tri + zeroed diag band
__device__ float g_invz[(size_t)Hc * Lc];        // 1/Z per (h,i)
__device__ float g_xr[(size_t)Bc * Lc * Dc];     // x rounded to tf32
__device__ float g_sfx[(size_t)Bc * Lc * Dc];    // suffix sums S[b,i,d]
__device__ float g_part[(size_t)Bc * SEGS * Dc]; // per-segment partial sums
__device__ float g_wpr[(size_t)Dc * Dc];         // W_proj rounded to tf32
__device__ float g_mixed[(size_t)Bc * Lc * Dc];  // mixing output (tf32-rounded)

__device__ __forceinline__ float tf32r(float x) {
    uint32_t u;
    asm("cvt.rna.tf32.f32 %0, %1;" : "=r"(u) : "f"(x));
    return __uint_as_float(u);
}

__device__ __forceinline__ void cpa16(void* smem, const void* g) {
    uint32_t s = (uint32_t)__cvta_generic_to_shared(smem);
    asm volatile("cp.async.cg.shared.global [%0], [%1], 16;\n" :: "r"(s), "l"(g) : "memory");
}
__device__ __forceinline__ void cp_commit() {
    asm volatile("cp.async.commit_group;\n" ::: "memory");
}

#define MMA_TF32(d, a, b) \
    asm volatile("mma.sync.aligned.m16n8k8.row.col.f32.tf32.tf32.f32 " \
        "{%0,%1,%2,%3}, {%4,%5,%6,%7}, {%8,%9}, {%0,%1,%2,%3};" \
        : "+f"((d)[0]), "+f"((d)[1]), "+f"((d)[2]), "+f"((d)[3]) \
        : "r"((a)[0]), "r"((a)[1]), "r"((a)[2]), "r"((a)[3]), \
          "r"((b)[0]), "r"((b)[1]))

// ---------------------------------------------------------------------------
// Round fp32 -> tf32 (rna) elementwise, vectorized (used for W_proj)
// ---------------------------------------------------------------------------
__global__ void round_tf32_kernel(const float* __restrict__ src,
                                  float* __restrict__ dst, int n4) {
    int i = blockIdx.x * blockDim.x + threadIdx.x;
    if (i < n4) {
        float4 v = reinterpret_cast<const float4*>(src)[i];
        v.x = tf32r(v.x); v.y = tf32r(v.y); v.z = tf32r(v.z); v.w = tf32r(v.w);
        reinterpret_cast<float4*>(dst)[i] = v;
    }
}

// ---------------------------------------------------------------------------
// Masked-softmax pieces: exp(W) lower-tri (tf32) + zeros in diag band, invZ.
// One block per (h, i) row.
// ---------------------------------------------------------------------------
__global__ void softmax_rows_kernel(const float* __restrict__ W) {
    __shared__ float ex[Lc];
    __shared__ float red[9];
    const int row = blockIdx.x;                 // h*L + i
    const int i = row & (Lc - 1);
    const float* wr = W + (size_t)row * Lc;
    float* outp = g_nw + (size_t)row * Lc;

    float s = 0.f;
    for (int l = threadIdx.x; l <= i; l += blockDim.x) {
        float e = __expf(wr[l]);
        ex[l] = e;
        s += e;
    }

    #pragma unroll
    for (int o = 16; o; o >>= 1) s += __shfl_xor_sync(0xffffffffu, s, o);
    if ((threadIdx.x & 31) == 0) red[threadIdx.x >> 5] = s;
    __syncthreads();
    if (threadIdx.x < 32) {
        float v = (threadIdx.x < 8) ? red[threadIdx.x] : 0.f;
        #pragma unroll
        for (int o = 4; o; o >>= 1) v += __shfl_xor_sync(0xffffffffu, v, o);
        if (threadIdx.x == 0) {
            float invZ = 1.f / (v + (float)(Lc - 1 - i));
            red[8] = invZ;
            g_invz[row] = invZ;
        }
    }
    __syncthreads();
    const int lim = (i | 127) + 1;   // end of this row's 128-block (diag band)
    for (int l = threadIdx.x; l < lim; l += blockDim.x)
        outp[l] = (l <= i) ? tf32r(ex[l]) : 0.f;
}

// ---------------------------------------------------------------------------
// Suffix-scan pass 1: per-segment partial sums of x (also writes tf32 x).
// grid (B, SEGS, Dc/256), block 256 (one thread per d)
// ---------------------------------------------------------------------------
__global__ void suffix_pass1_kernel(const float* __restrict__ x) {
    const int b = blockIdx.x, seg = blockIdx.y;
    const int d = blockIdx.z * 256 + threadIdx.x;
    const size_t base = ((size_t)b * Lc + seg * SEGL) * Dc + d;
    const float* xp = x + base;
    float* xrp = g_xr + base;
    float s = 0.f;
    #pragma unroll 4
    for (int j = 0; j < SEGL; j++) {
        float v = tf32r(xp[(size_t)j * Dc]);
        xrp[(size_t)j * Dc] = v;
        s += v;
    }
    g_part[((size_t)b * SEGS + seg) * Dc + d] = s;
}

// ---------------------------------------------------------------------------
// Suffix-scan pass 2: S[b,i,d] = sum_{l>i} xr[b,l,d]
// ---------------------------------------------------------------------------
__global__ void suffix_pass2_kernel() {
    const int b = blockIdx.x, seg = blockIdx.y;
    const int d = blockIdx.z * 256 + threadIdx.x;
    float run = 0.f;
    for (int s2 = seg + 1; s2 < SEGS; s2++)
        run += g_part[((size_t)b * SEGS + s2) * Dc + d];
    const size_t base = ((size_t)b * Lc + seg * SEGL) * Dc + d;
    const float* xrp = g_xr + base;
    float* sp = g_sfx + base;
    #pragma unroll 4
    for (int j = SEGL - 1; j >= 0; j--) {
        sp[(size_t)j * Dc] = run;
        run += xrp[(size_t)j * Dc];
    }
}

// ---------------------------------------------------------------------------
// GEMM 1: per-head lower-triangular mixing.
//   acc[i,n] = sum_{l<blockdiag} E_h[i,l] * X[b,l,h*64+dd]
//   mixed    = (acc + S) * invZ
// M=2048, N=512, K_eff triangular, tf32 mma, 128x128x32 tiles.
// ---------------------------------------------------------------------------
__global__ void __launch_bounds__(256, 2) gemm_mix_kernel() {
    constexpr int BM = 128, BN = 128, BK = 32;
    constexpr int AP = BK + 4;   // As pitch (floats)
    constexpr int BP = BN + 8;   // Bs pitch (floats)
    extern __shared__ float sm[];
    float (*As)[BM][AP] = reinterpret_cast<float (*)[BM][AP]>(sm);
    float (*Bs)[BK][BP] = reinterpret_cast<float (*)[BK][BP]>(sm + 2 * BM * AP);

    const int h  = blockIdx.z;
    const int m0 = (gridDim.y - 1 - blockIdx.y) * BM;   // heavy rows first
    const int n0 = blockIdx.x * BN;
    const int tid = threadIdx.x;
    const int lane = tid & 31, warp = tid >> 5;
    const int wm = warp & 3, wn = warp >> 2;

    const float* Ag = g_nw + (size_t)h * Lc * Lc;
    const int ar = tid >> 3;            // A: 0..31 row-in-pass
    const int ac = (tid & 7) * 4;       // A: col
    const int br = tid >> 5;            // B: 0..7 k-row-in-pass
    const int bc = (tid & 31) * 4;      // B: n col
    const int nb = (n0 + bc) >> 6;      // batch
    const int dd = (n0 + bc) & 63;
    const float* Bg = g_xr + (size_t)nb * Lc * Dc + (size_t)h * dhc + dd;

    float acc[2][8][4];
    #pragma unroll
    for (int a = 0; a < 2; a++)
        #pragma unroll
        for (int b = 0; b < 8; b++)
            #pragma unroll
            for (int c = 0; c < 4; c++) acc[a][b][c] = 0.f;

    const int nkt = (m0 + BM) / BK;     // triangular: only k-tiles below diag band

    auto load_tiles = [&](int buf, int kt) {
        #pragma unroll
        for (int p = 0; p < 4; p++) {
            int row = p * 32 + ar;
            cpa16(&As[buf][row][ac], Ag + (size_t)(m0 + row) * Lc + kt * BK + ac);
        }
        #pragma unroll
        for (int p = 0; p < 4; p++) {
            int krow = p * 8 + br;
            cpa16(&Bs[buf][krow][bc], Bg + (size_t)(kt * BK + krow) * Dc);
        }
        cp_commit();
    };

    load_tiles(0, 0);
    for (int kt = 0; kt < nkt; kt++) {
        const int buf = kt & 1;
        if (kt + 1 < nkt) {
            load_tiles(buf ^ 1, kt + 1);
            asm volatile("cp.async.wait_group 1;\n" ::: "memory");
        } else {
            asm volatile("cp.async.wait_group 0;\n" ::: "memory");
        }
        __syncthreads();

        const int r = lane >> 2, c = lane & 3;
        #pragma unroll
        for (int ks = 0; ks < 4; ks++) {
            const int kc = ks * 8;
            uint32_t afr[2][4], bfr[8][2];
            #pragma unroll
            for (int mt = 0; mt < 2; mt++) {
                const int rb = wm * 32 + mt * 16;
                afr[mt][0] = __float_as_uint(As[buf][rb + r][kc + c]);
                afr[mt][1] = __float_as_uint(As[buf][rb + r + 8][kc + c]);
                afr[mt][2] = __float_as_uint(As[buf][rb + r][kc + c + 4]);
                afr[mt][3] = __float_as_uint(As[buf][rb + r + 8][kc + c + 4]);
            }
            #pragma unroll
            for (int nt = 0; nt < 8; nt++) {
                const int cb = wn * 64 + nt * 8;
                bfr[nt][0] = __float_as_uint(Bs[buf][kc + c][cb + r]);
                bfr[nt][1] = __float_as_uint(Bs[buf][kc + c + 4][cb + r]);
            }
            #pragma unroll
            for (int mt = 0; mt < 2; mt++)
                #pragma unroll
                for (int nt = 0; nt < 8; nt++)
                    MMA_TF32(acc[mt][nt], afr[mt], bfr[nt]);
        }
        __syncthreads();
    }

    // epilogue: mixed[b, i, h*64+dd] = (acc + S) * invZ, tf32-rounded for GEMM2
    const int r = lane >> 2, c2 = (lane & 3) * 2;
    #pragma unroll
    for (int mt = 0; mt < 2; mt++) {
        const int row = m0 + wm * 32 + mt * 16 + r;
        const float iz0 = g_invz[(size_t)h * Lc + row];
        const float iz1 = g_invz[(size_t)h * Lc + row + 8];
        #pragma unroll
        for (int nt = 0; nt < 8; nt++) {
            const int col = n0 + wn * 64 + nt * 8 + c2;
            const int b = col >> 6, d0 = col & 63;
            const size_t base = ((size_t)b * Lc + row) * Dc + h * dhc + d0;
            float* o0 = g_mixed + base;
            const float* s0 = g_sfx + base;
            o0[0] = tf32r((acc[mt][nt][0] + s0[0]) * iz0);
            o0[1] = tf32r((acc[mt][nt][1] + s0[1]) * iz0);
            float* o1 = o0 + 8 * Dc;
            const float* s1 = s0 + 8 * Dc;
            o1[0] = tf32r((acc[mt][nt][2] + s1[0]) * iz1);
            o1[1] = tf32r((acc[mt][nt][3] + s1[1]) * iz1);
        }
    }
}

// ---------------------------------------------------------------------------
// GEMM 2: projection.  out[m, j] = sum_k mixed[m, k] * W_proj[j, k] + b[j]
// M=16384, N=1024, K=1024.
// ---------------------------------------------------------------------------
__global__ void __launch_bounds__(256, 2) gemm_proj_kernel(
    const float* __restrict__ bias, float* __restrict__ out) {
    constexpr int BM = 128, BN = 128, BK = 32;
    constexpr int AP = BK + 4;
    extern __shared__ float sm[];
    float (*As)[BM][AP] = reinterpret_cast<float (*)[BM][AP]>(sm);
    float (*Bs)[BM][AP] = reinterpret_cast<float (*)[BM][AP]>(sm + 2 * BM * AP);

    const int m0 = blockIdx.y * BM;
    const int n0 = blockIdx.x * BN;
    const int tid = threadIdx.x;
    const int lane = tid & 31, warp = tid >> 5;
    const int wm = warp & 3, wn = warp >> 2;

    const int ar = tid >> 3;
    const int ac = (tid & 7) * 4;

    float acc[2][8][4];
    #pragma unroll
    for (int a = 0; a < 2; a++)
        #pragma unroll
        for (int b = 0; b < 8; b++)
            #pragma unroll
            for (int c = 0; c < 4; c++) acc[a][b][c] = 0.f;

    const int nkt = Dc / BK;            // 32

    auto load_tiles = [&](int buf, int kt) {
        #pragma unroll
        for (int p = 0; p < 4; p++) {
            int row = p * 32 + ar;
            cpa16(&As[buf][row][ac], g_mixed + (size_t)(m0 + row) * Dc + kt * BK + ac);
            cpa16(&Bs[buf][row][ac], g_wpr   + (size_t)(n0 + row) * Dc + kt * BK + ac);
        }
        cp_commit();
    };

    load_tiles(0, 0);
    for (int kt = 0; kt < nkt; kt++) {
        const int buf = kt & 1;
        if (kt + 1 < nkt) {
            load_tiles(buf ^ 1, kt + 1);
            asm volatile("cp.async.wait_group 1;\n" ::: "memory");
        } else {
            asm volatile("cp.async.wait_group 0;\n" ::: "memory");
        }
        __syncthreads();

        const int r = lane >> 2, c = lane & 3;
        #pragma unroll
        for (int ks = 0; ks < 4; ks++) {
            const int kc = ks * 8;
            uint32_t afr[2][4], bfr[8][2];
            #pragma unroll
            for (int mt = 0; mt < 2; mt++) {
                const int rb = wm * 32 + mt * 16;
                afr[mt][0] = __float_as_uint(As[buf][rb + r][kc + c]);
                afr[mt][1] = __float_as_uint(As[buf][rb + r + 8][kc + c]);
                afr[mt][2] = __float_as_uint(As[buf][rb + r][kc + c + 4]);
                afr[mt][3] = __float_as_uint(As[buf][rb + r + 8][kc + c + 4]);
            }
            #pragma unroll
            for (int nt = 0; nt < 8; nt++) {
                const int cb = wn * 64 + nt * 8;
                bfr[nt][0] = __float_as_uint(Bs[buf][cb + r][kc + c]);
                bfr[nt][1] = __float_as_uint(Bs[buf][cb + r][kc + c + 4]);
            }
            #pragma unroll
            for (int mt = 0; mt < 2; mt++)
                #pragma unroll
                for (int nt = 0; nt < 8; nt++)
                    MMA_TF32(acc[mt][nt], afr[mt], bfr[nt]);
        }
        __syncthreads();
    }

    const int r = lane >> 2, c2 = (lane & 3) * 2;
    #pragma unroll
    for (int mt = 0; mt < 2; mt++) {
        #pragma unroll
        for (int nt = 0; nt < 8; nt++) {
            const int row = m0 + wm * 32 + mt * 16 + r;
            const int col = n0 + wn * 64 + nt * 8 + c2;
            const float bz0 = bias[col], bz1 = bias[col + 1];
            float* o0 = out + (size_t)row * Dc + col;
            o0[0] = acc[mt][nt][0] + bz0;
            o0[1] = acc[mt][nt][1] + bz1;
            float* o1 = o0 + 8 * Dc;
            o1[0] = acc[mt][nt][2] + bz0;
            o1[1] = acc[mt][nt][3] + bz1;
        }
    }
}

// ---------------------------------------------------------------------------
extern "C" void kernel_launch(void* const* d_in, const int* in_sizes, int n_in,
                              void* d_out, int out_size) {
    const float* x  = (const float*)d_in[0];
    const float* W  = (const float*)d_in[1];
    const float* Wp = (const float*)d_in[2];
    const float* bp = (const float*)d_in[3];
    float* out = (float*)d_out;

    float* wpr_p = nullptr;
    cudaGetSymbolAddress((void**)&wpr_p, g_wpr);

    constexpr int SMEM_MIX  = 2 * 128 * 36 * 4 + 2 * 32 * 136 * 4;   // 71680
    constexpr int SMEM_PROJ = 2 * 128 * 36 * 4 + 2 * 128 * 36 * 4;   // 73728
    cudaFuncSetAttribute(gemm_mix_kernel,
                         cudaFuncAttributeMaxDynamicSharedMemorySize, SMEM_MIX);
    cudaFuncSetAttribute(gemm_proj_kernel,
                         cudaFuncAttributeMaxDynamicSharedMemorySize, SMEM_PROJ);

    // 1) round W_proj to tf32
    {
        int n4 = Dc * Dc / 4;
        round_tf32_kernel<<<(n4 + 255) / 256, 256>>>(Wp, wpr_p, n4);
    }
    // 2) masked softmax pieces -> g_nw (exp, lower-tri), g_invz
    softmax_rows_kernel<<<Hc * Lc, 256>>>(W);
    // 3) suffix scan (also rounds x -> g_xr)
    suffix_pass1_kernel<<<dim3(Bc, SEGS, Dc / 256), 256>>>(x);
    suffix_pass2_kernel<<<dim3(Bc, SEGS, Dc / 256), 256>>>();
    // 4) per-head triangular mixing GEMM -> g_mixed
    gemm_mix_kernel<<<dim3(Nmix / 128, Lc / 128, Hc), 256, SMEM_MIX>>>();
    // 5) projection GEMM + bias -> out
    gemm_proj_kernel<<<dim3(Dc / 128, (Bc * Lc) / 128), 256, SMEM_PROJ>>>(bp, out);
}